// round 3
// baseline (speedup 1.0000x reference)
#include <cuda_runtime.h>

#define HNUM 16
#define NSEQ 2048
#define DDIM 64
#define CHK  64                 // phase3 chunk
#define SUB  32                 // phase1 sub-chunk rows
#define NC   (NSEQ / CHK)       // 32 chunks / head
#define NSC  (NSEQ / SUB)       // 64 sub-chunks / head
#define NB   (HNUM * NC)        // 512 phase3 tiles
#define NBP  (HNUM * NSC)       // 1024 phase1 tiles
#define EPSV 1e-6f

#define ST 68                   // padded stride (keeps float4 alignment)

// Scratch
__device__ float g_KVp[(size_t)NBP * DDIM * DDIM];  // per-sub-chunk KV (16 MB)
__device__ float g_Kzp[(size_t)NBP * DDIM];         // per-sub-chunk K colsum
__device__ float g_S[(size_t)NB * DDIM * DDIM];     // exclusive prefix per chunk (8 MB)
__device__ float g_z[(size_t)NB * DDIM];            // exclusive prefix colsum

__device__ __forceinline__ float fmap(float x) {
    // elu(x) + 1 : x>0 -> x+1 ; x<=0 -> exp(x)
    return x > 0.f ? x + 1.f : __expf(x);
}

// ---------------------------------------------------------------------------
// Phase 1: per-SUB-chunk KV = phiK^T V (64x64) and Kz = colsum(phiK)
// grid = NBP (1024), block = 128, 8x4 register tiles
// ---------------------------------------------------------------------------
__global__ void __launch_bounds__(128) lin_phase1(const float* __restrict__ Kg,
                                                  const float* __restrict__ Vg) {
    __shared__ float sK[SUB * DDIM];
    __shared__ float sV[SUB * DDIM];
    const int tid = threadIdx.x;
    const size_t base = (size_t)blockIdx.x * (SUB * DDIM);

    #pragma unroll
    for (int s = 0; s < 4; s++) {
        int i4 = tid + s * 128;                 // 512 float4 per tensor
        float4 k = ((const float4*)(Kg + base))[i4];
        float4 v = ((const float4*)(Vg + base))[i4];
        k.x = fmap(k.x); k.y = fmap(k.y); k.z = fmap(k.z); k.w = fmap(k.w);
        ((float4*)sK)[i4] = k;
        ((float4*)sV)[i4] = v;
    }
    __syncthreads();

    const int d0 = (tid >> 4) * 8;   // 8 d-groups of 8
    const int e0 = (tid & 15) * 4;   // 16 e-groups of 4
    float acc[8][4] = {};
    #pragma unroll 4
    for (int m = 0; m < SUB; m++) {
        float4 k0 = *(const float4*)&sK[m * DDIM + d0];
        float4 k1 = *(const float4*)&sK[m * DDIM + d0 + 4];
        float4 vf = *(const float4*)&sV[m * DDIM + e0];
        float kk[8] = {k0.x, k0.y, k0.z, k0.w, k1.x, k1.y, k1.z, k1.w};
        float vv[4] = {vf.x, vf.y, vf.z, vf.w};
        #pragma unroll
        for (int a = 0; a < 8; a++)
            #pragma unroll
            for (int b = 0; b < 4; b++)
                acc[a][b] += kk[a] * vv[b];
    }

    float* kvo = g_KVp + (size_t)blockIdx.x * (DDIM * DDIM);
    #pragma unroll
    for (int a = 0; a < 8; a++)
        *(float4*)&kvo[(d0 + a) * DDIM + e0] =
            make_float4(acc[a][0], acc[a][1], acc[a][2], acc[a][3]);

    if (tid < DDIM) {
        float s = 0.f;
        #pragma unroll 8
        for (int m = 0; m < SUB; m++) s += sK[m * DDIM + tid];
        g_Kzp[(size_t)blockIdx.x * DDIM + tid] = s;
    }
}

// ---------------------------------------------------------------------------
// Phase 2: scan 64 sub-chunk states per head; emit EXCLUSIVE prefix at each
// CHK (=2 sub-chunk) boundary. grid = 16 heads * 8 parts, block = 512
// ---------------------------------------------------------------------------
__global__ void __launch_bounds__(512) lin_phase2() {
    const int h = blockIdx.x >> 3;
    const int part = blockIdx.x & 7;
    const int idx = part * 512 + threadIdx.x;   // 0..4095

    float run = 0.f;
    #pragma unroll
    for (int sc = 0; sc < NSC; sc++) {
        if ((sc & 1) == 0)
            g_S[((size_t)h * NC + (sc >> 1)) * (DDIM * DDIM) + idx] = run;
        run += g_KVp[((size_t)h * NSC + sc) * (DDIM * DDIM) + idx];
    }
    if (part == 0 && threadIdx.x < DDIM) {
        float rz = 0.f;
        #pragma unroll
        for (int sc = 0; sc < NSC; sc++) {
            if ((sc & 1) == 0)
                g_z[(size_t)(h * NC + (sc >> 1)) * DDIM + threadIdx.x] = rz;
            rz += g_Kzp[(size_t)(h * NSC + sc) * DDIM + threadIdx.x];
        }
    }
}

// ---------------------------------------------------------------------------
// Phase 3: per chunk (C=64):
//   A      = phiQ @ phiK^T   (causal-masked, stored TRANSPOSED)
//   den[m] = rowsum(A) + phiQ[m].z_excl + EPS
//   out    = (A @ V + phiQ @ S_excl) / den
// grid = NB (512), block = 256.  sS aliases sKt (dead after A-phase);
// S prefetched to registers so the gmem latency hides under the A-GEMM.
// ---------------------------------------------------------------------------
__global__ void __launch_bounds__(256) lin_phase3(const float* __restrict__ Qg,
                                                  const float* __restrict__ Kg,
                                                  const float* __restrict__ Vg,
                                                  float* __restrict__ Og) {
    extern __shared__ float sm[];
    float* sQt  = sm;                   // [d][m] DDIM*ST
    float* sKt  = sQt + DDIM * ST;      // [d][j] DDIM*ST ; becomes sS after A
    float* sV   = sKt + DDIM * ST;      // [k][e] CHK*DDIM
    float* sAt  = sV  + CHK * DDIM;     // [k][m] CHK*ST (transposed, masked)
    float* sZ   = sAt + CHK * ST;       // DDIM
    float* sDen = sZ  + DDIM;           // CHK
    float* sS   = sKt;                  // alias

    const int tid = threadIdx.x;
    const size_t base = (size_t)blockIdx.x * (CHK * DDIM);

    // --- prefetch S_excl into registers (used only after A-phase) ---
    float4 sreg[4];
    {
        const float4* Sg4 = (const float4*)(g_S + (size_t)blockIdx.x * (DDIM * DDIM));
        #pragma unroll
        for (int s = 0; s < 4; s++) sreg[s] = Sg4[tid + s * 256];
    }

    // --- load + feature map + transpose Q,K; V row-major; z ---
    {
        const int m  = tid >> 2;          // 0..63
        const int d0 = (tid & 3) * 16;    // 0,16,32,48
        #pragma unroll
        for (int u = 0; u < 4; u++) {
            int col = d0 + 4 * u;
            float4 q = *(const float4*)(Qg + base + m * DDIM + col);
            float4 k = *(const float4*)(Kg + base + m * DDIM + col);
            float4 v = *(const float4*)(Vg + base + m * DDIM + col);
            sQt[(col + 0) * ST + m] = fmap(q.x);
            sQt[(col + 1) * ST + m] = fmap(q.y);
            sQt[(col + 2) * ST + m] = fmap(q.z);
            sQt[(col + 3) * ST + m] = fmap(q.w);
            sKt[(col + 0) * ST + m] = fmap(k.x);
            sKt[(col + 1) * ST + m] = fmap(k.y);
            sKt[(col + 2) * ST + m] = fmap(k.z);
            sKt[(col + 3) * ST + m] = fmap(k.w);
            *(float4*)&sV[m * DDIM + col] = v;
        }
        if (tid < DDIM) sZ[tid] = g_z[(size_t)blockIdx.x * DDIM + tid];
    }
    __syncthreads();

    const int rbase = (tid >> 4) * 4;   // output rows (m)
    const int cbase = (tid & 15) * 4;   // output cols (j / e)

    // --- A-phase: A[m][j] = sum_d phiQ[m][d] phiK[j][d]; store transposed ---
    {
        float acc[4][4] = {};
        #pragma unroll 8
        for (int d = 0; d < DDIM; d++) {
            float4 qf = *(const float4*)&sQt[d * ST + rbase];
            float4 kf = *(const float4*)&sKt[d * ST + cbase];
            float qq[4] = {qf.x, qf.y, qf.z, qf.w};
            float kk[4] = {kf.x, kf.y, kf.z, kf.w};
            #pragma unroll
            for (int a = 0; a < 4; a++)
                #pragma unroll
                for (int b = 0; b < 4; b++)
                    acc[a][b] += qq[a] * kk[b];
        }
        #pragma unroll
        for (int b = 0; b < 4; b++) {
            int col = cbase + b;
            float4 o;
            o.x = (col <= rbase + 0) ? acc[0][b] : 0.f;
            o.y = (col <= rbase + 1) ? acc[1][b] : 0.f;
            o.z = (col <= rbase + 2) ? acc[2][b] : 0.f;
            o.w = (col <= rbase + 3) ? acc[3][b] : 0.f;
            *(float4*)&sAt[col * ST + rbase] = o;
        }
    }
    __syncthreads();

    // --- spill S registers into (dead) sKt buffer; denominator ---
    {
        #pragma unroll
        for (int s = 0; s < 4; s++) ((float4*)sS)[tid + s * 256] = sreg[s];
        if (tid < CHK) {
            float s = EPSV;
            #pragma unroll 4
            for (int k = 0; k <= tid; k++) s += sAt[k * ST + tid];
            #pragma unroll 8
            for (int d = 0; d < DDIM; d++) s += sQt[d * ST + tid] * sZ[d];
            sDen[tid] = 1.f / s;
        }
    }
    __syncthreads();

    // --- B-phase: out = A@V + phiQ@S ; causal k-loop truncated per warp ---
    {
        const int kmax = ((tid >> 5) + 1) * 8;   // warp w owns rows 8w..8w+7
        float acc[4][4] = {};
        #pragma unroll 8
        for (int k = 0; k < kmax; k++) {
            float4 af = *(const float4*)&sAt[k * ST + rbase];
            float4 vf = *(const float4*)&sV[k * DDIM + cbase];
            float aa[4] = {af.x, af.y, af.z, af.w};
            float vv[4] = {vf.x, vf.y, vf.z, vf.w};
            #pragma unroll
            for (int a = 0; a < 4; a++)
                #pragma unroll
                for (int b = 0; b < 4; b++)
                    acc[a][b] += aa[a] * vv[b];
        }
        #pragma unroll 8
        for (int d = 0; d < DDIM; d++) {
            float4 qf = *(const float4*)&sQt[d * ST + rbase];
            float4 sf = *(const float4*)&sS[d * DDIM + cbase];
            float qq[4] = {qf.x, qf.y, qf.z, qf.w};
            float ss[4] = {sf.x, sf.y, sf.z, sf.w};
            #pragma unroll
            for (int a = 0; a < 4; a++)
                #pragma unroll
                for (int b = 0; b < 4; b++)
                    acc[a][b] += qq[a] * ss[b];
        }
        #pragma unroll
        for (int a = 0; a < 4; a++) {
            float inv = sDen[rbase + a];
            *(float4*)&Og[base + (size_t)(rbase + a) * DDIM + cbase] =
                make_float4(acc[a][0] * inv, acc[a][1] * inv,
                            acc[a][2] * inv, acc[a][3] * inv);
        }
    }
}

// ---------------------------------------------------------------------------
extern "C" void kernel_launch(void* const* d_in, const int* in_sizes, int n_in,
                              void* d_out, int out_size) {
    const float* Q = (const float*)d_in[0];
    const float* K = (const float*)d_in[1];
    const float* V = (const float*)d_in[2];
    float* O = (float*)d_out;

    const int SMEM3 = (2 * DDIM * ST + CHK * DDIM + CHK * ST + DDIM + CHK)
                      * (int)sizeof(float);   // 69,120 B -> 3 CTAs/SM

    static int inited = 0;
    if (!inited) {
        cudaFuncSetAttribute(lin_phase3, cudaFuncAttributeMaxDynamicSharedMemorySize, SMEM3);
        inited = 1;
    }

    lin_phase1<<<NBP, 128>>>(K, V);
    lin_phase2<<<HNUM * 8, 512>>>();
    lin_phase3<<<NB, 256, SMEM3>>>(Q, K, V, O);
}

// round 4
// speedup vs baseline: 1.7598x; 1.7598x over previous
#include <cuda_runtime.h>

#define HNUM 16
#define NSEQ 2048
#define DDIM 64
#define CHK  64
#define NC   (NSEQ / CHK)      // 32 chunks
#define NB   (HNUM * NC)       // 512 (head, chunk) tiles
#define EPSV 1e-6f

#define ST 68                  // padded stride for transposed tiles / A

// Scratch: per-(head,chunk) KV state (64x64) and K feature-sum (64).
// Phase 1 writes per-chunk sums; phase 2 converts in place to EXCLUSIVE prefix.
__device__ float g_KV[(size_t)NB * DDIM * DDIM];   // 8 MB
__device__ float g_Kz[(size_t)NB * DDIM];          // 128 KB

__device__ __forceinline__ float fmap(float x) {
    // elu(x) + 1 : x>0 -> x+1 ; x<=0 -> exp(x)
    return x > 0.f ? x + 1.f : __expf(x);
}

// ---------------------------------------------------------------------------
// Phase 1: per-chunk KV = phiK^T V  (64x64)  and Kz = colsum(phiK)
// grid = NB (512), block = 256    [verbatim Round-2 version: measured 14.8us]
// ---------------------------------------------------------------------------
__global__ void __launch_bounds__(256) lin_phase1(const float* __restrict__ Kg,
                                                  const float* __restrict__ Vg) {
    extern __shared__ float sm[];
    float* sK = sm;                    // CHK*DDIM phiK (row-major)
    float* sV = sm + CHK * DDIM;       // CHK*DDIM
    const int tid = threadIdx.x;
    const size_t base = (size_t)blockIdx.x * (CHK * DDIM);

    #pragma unroll
    for (int s = 0; s < 4; s++) {
        int i4 = tid + s * 256;                 // float4 index, 1024 total
        float4 k = ((const float4*)(Kg + base))[i4];
        float4 v = ((const float4*)(Vg + base))[i4];
        k.x = fmap(k.x); k.y = fmap(k.y); k.z = fmap(k.z); k.w = fmap(k.w);
        ((float4*)sK)[i4] = k;
        ((float4*)sV)[i4] = v;
    }
    __syncthreads();

    const int d0 = (tid >> 4) * 4;
    const int e0 = (tid & 15) * 4;
    float acc[4][4] = {};
    #pragma unroll 8
    for (int m = 0; m < CHK; m++) {
        float4 kf = *(const float4*)&sK[m * DDIM + d0];
        float4 vf = *(const float4*)&sV[m * DDIM + e0];
        float kk[4] = {kf.x, kf.y, kf.z, kf.w};
        float vv[4] = {vf.x, vf.y, vf.z, vf.w};
        #pragma unroll
        for (int a = 0; a < 4; a++)
            #pragma unroll
            for (int b = 0; b < 4; b++)
                acc[a][b] += kk[a] * vv[b];
    }

    float* kvo = g_KV + (size_t)blockIdx.x * (DDIM * DDIM);
    #pragma unroll
    for (int a = 0; a < 4; a++)
        *(float4*)&kvo[(d0 + a) * DDIM + e0] =
            make_float4(acc[a][0], acc[a][1], acc[a][2], acc[a][3]);

    if (tid < DDIM) {
        float s = 0.f;
        #pragma unroll 8
        for (int m = 0; m < CHK; m++) s += sK[m * DDIM + tid];
        g_Kz[(size_t)blockIdx.x * DDIM + tid] = s;
    }
}

// ---------------------------------------------------------------------------
// Phase 2: in-place exclusive prefix over 32 chunks (per head), float4-wide.
// grid = 16 heads * 8 parts = 128, block = 128
// ---------------------------------------------------------------------------
__global__ void __launch_bounds__(128) lin_phase2() {
    const int h = blockIdx.x >> 3;
    const int part = blockIdx.x & 7;
    const int i4 = part * 128 + threadIdx.x;    // 0..1023 float4 index

    float4 run = make_float4(0.f, 0.f, 0.f, 0.f);
    #pragma unroll
    for (int c = 0; c < NC; c++) {
        float4* p = (float4*)(g_KV + ((size_t)(h * NC + c)) * (DDIM * DDIM)) + i4;
        float4 v = *p;
        *p = run;
        run.x += v.x; run.y += v.y; run.z += v.z; run.w += v.w;
    }
    if (part == 0 && threadIdx.x < DDIM / 4) {  // 16 float4 per head for z
        float4 rz = make_float4(0.f, 0.f, 0.f, 0.f);
        #pragma unroll
        for (int c = 0; c < NC; c++) {
            float4* p = (float4*)(g_Kz + (size_t)(h * NC + c) * DDIM) + threadIdx.x;
            float4 v = *p;
            *p = rz;
            rz.x += v.x; rz.y += v.y; rz.z += v.z; rz.w += v.w;
        }
    }
}

// ---------------------------------------------------------------------------
// Phase 3: per chunk (C=64):
//   A      = phiQ @ phiK^T   (64x64, causal-masked, stored TRANSPOSED)
//   den[m] = rowsum(A) + phiQ[m].z_excl + EPS
//   out    = (A @ V + phiQ @ S_excl) / den
// grid = NB (512), block = 256.
// sS aliases sKt (dead after A-phase); S loaded from gmem AFTER the A-phase
// sync (latency covered by co-resident CTAs; 3 CTAs/SM at 67.5 KB smem).
// ---------------------------------------------------------------------------
__global__ void __launch_bounds__(256) lin_phase3(const float* __restrict__ Qg,
                                                  const float* __restrict__ Kg,
                                                  const float* __restrict__ Vg,
                                                  float* __restrict__ Og) {
    extern __shared__ float sm[];
    float* sQt  = sm;                   // [d][m] DDIM*ST
    float* sKt  = sQt + DDIM * ST;      // [d][j] DDIM*ST ; becomes sS after A
    float* sV   = sKt + DDIM * ST;      // [k][e] CHK*DDIM
    float* sAt  = sV  + CHK * DDIM;     // [k][m] CHK*ST (transposed, masked)
    float* sZ   = sAt + CHK * ST;       // DDIM
    float* sDen = sZ  + DDIM;           // CHK
    float* sS   = sKt;                  // alias: [d][e] DDIM*DDIM (<= DDIM*ST)

    const int tid = threadIdx.x;
    const size_t base = (size_t)blockIdx.x * (CHK * DDIM);

    // --- load + feature map + transpose Q,K; V row-major; z ---
    {
        const int m  = tid >> 2;          // 0..63
        const int d0 = (tid & 3) * 16;    // 0,16,32,48
        #pragma unroll
        for (int u = 0; u < 4; u++) {
            int col = d0 + 4 * u;
            float4 q = *(const float4*)(Qg + base + m * DDIM + col);
            float4 k = *(const float4*)(Kg + base + m * DDIM + col);
            float4 v = *(const float4*)(Vg + base + m * DDIM + col);
            sQt[(col + 0) * ST + m] = fmap(q.x);
            sQt[(col + 1) * ST + m] = fmap(q.y);
            sQt[(col + 2) * ST + m] = fmap(q.z);
            sQt[(col + 3) * ST + m] = fmap(q.w);
            sKt[(col + 0) * ST + m] = fmap(k.x);
            sKt[(col + 1) * ST + m] = fmap(k.y);
            sKt[(col + 2) * ST + m] = fmap(k.z);
            sKt[(col + 3) * ST + m] = fmap(k.w);
            *(float4*)&sV[m * DDIM + col] = v;
        }
        if (tid < DDIM) sZ[tid] = g_Kz[(size_t)blockIdx.x * DDIM + tid];
    }
    __syncthreads();

    const int rbase = (tid >> 4) * 4;   // output rows (m)
    const int cbase = (tid & 15) * 4;   // output cols (j / e)

    // --- A-phase: A[m][j] = sum_d phiQ[m][d] phiK[j][d]; store transposed ---
    {
        float acc[4][4] = {};
        #pragma unroll 8
        for (int d = 0; d < DDIM; d++) {
            float4 qf = *(const float4*)&sQt[d * ST + rbase];
            float4 kf = *(const float4*)&sKt[d * ST + cbase];
            float qq[4] = {qf.x, qf.y, qf.z, qf.w};
            float kk[4] = {kf.x, kf.y, kf.z, kf.w};
            #pragma unroll
            for (int a = 0; a < 4; a++)
                #pragma unroll
                for (int b = 0; b < 4; b++)
                    acc[a][b] += qq[a] * kk[b];
        }
        #pragma unroll
        for (int b = 0; b < 4; b++) {
            int col = cbase + b;
            float4 o;
            o.x = (col <= rbase + 0) ? acc[0][b] : 0.f;
            o.y = (col <= rbase + 1) ? acc[1][b] : 0.f;
            o.z = (col <= rbase + 2) ? acc[2][b] : 0.f;
            o.w = (col <= rbase + 3) ? acc[3][b] : 0.f;
            *(float4*)&sAt[col * ST + rbase] = o;
        }
    }
    __syncthreads();

    // --- load S into the (dead) sKt buffer; denominator ---
    {
        const float4* Sg4 = (const float4*)(g_KV + (size_t)blockIdx.x * (DDIM * DDIM));
        #pragma unroll
        for (int s = 0; s < 4; s++)
            ((float4*)sS)[tid + s * 256] = Sg4[tid + s * 256];
        if (tid < CHK) {
            float s = EPSV;
            #pragma unroll 8
            for (int k = 0; k < CHK; k++) s += sAt[k * ST + tid];
            #pragma unroll 8
            for (int d = 0; d < DDIM; d++) s += sQt[d * ST + tid] * sZ[d];
            sDen[tid] = 1.f / s;
        }
    }
    __syncthreads();

    // --- B-phase: out = A@V + phiQ@S (fully static loops) ---
    {
        float acc[4][4] = {};
        #pragma unroll 8
        for (int k = 0; k < CHK; k++) {
            float4 af = *(const float4*)&sAt[k * ST + rbase];
            float4 vf = *(const float4*)&sV[k * DDIM + cbase];
            float aa[4] = {af.x, af.y, af.z, af.w};
            float vv[4] = {vf.x, vf.y, vf.z, vf.w};
            #pragma unroll
            for (int a = 0; a < 4; a++)
                #pragma unroll
                for (int b = 0; b < 4; b++)
                    acc[a][b] += aa[a] * vv[b];
        }
        #pragma unroll 8
        for (int d = 0; d < DDIM; d++) {
            float4 qf = *(const float4*)&sQt[d * ST + rbase];
            float4 sf = *(const float4*)&sS[d * DDIM + cbase];
            float qq[4] = {qf.x, qf.y, qf.z, qf.w};
            float ss[4] = {sf.x, sf.y, sf.z, sf.w};
            #pragma unroll
            for (int a = 0; a < 4; a++)
                #pragma unroll
                for (int b = 0; b < 4; b++)
                    acc[a][b] += qq[a] * ss[b];
        }
        #pragma unroll
        for (int a = 0; a < 4; a++) {
            float inv = sDen[rbase + a];
            *(float4*)&Og[base + (size_t)(rbase + a) * DDIM + cbase] =
                make_float4(acc[a][0] * inv, acc[a][1] * inv,
                            acc[a][2] * inv, acc[a][3] * inv);
        }
    }
}

// ---------------------------------------------------------------------------
extern "C" void kernel_launch(void* const* d_in, const int* in_sizes, int n_in,
                              void* d_out, int out_size) {
    const float* Q = (const float*)d_in[0];
    const float* K = (const float*)d_in[1];
    const float* V = (const float*)d_in[2];
    float* O = (float*)d_out;

    const int SMEM1 = 2 * CHK * DDIM * (int)sizeof(float);                   // 32 KB
    const int SMEM3 = (2 * DDIM * ST + CHK * DDIM + CHK * ST + DDIM + CHK)
                      * (int)sizeof(float);                                  // 67.5 KB

    static int inited = 0;
    if (!inited) {
        cudaFuncSetAttribute(lin_phase1, cudaFuncAttributeMaxDynamicSharedMemorySize, SMEM1);
        cudaFuncSetAttribute(lin_phase3, cudaFuncAttributeMaxDynamicSharedMemorySize, SMEM3);
        inited = 1;
    }

    lin_phase1<<<NB, 256, SMEM1>>>(K, V);
    lin_phase2<<<HNUM * 8, 128>>>();
    lin_phase3<<<NB, 256, SMEM3>>>(Q, K, V, O);
}